// round 14
// baseline (speedup 1.0000x reference)
#include <cuda_runtime.h>
#include <cstdint>

#define N_NODES 100000
#define E_MAX   3200000
#define F_IN    495
#define FH      16

// ---- scratch (no device allocations allowed) ----
static __device__ int    d_cnt [N_NODES];        // zero-initialized at load; re-zeroed by k_edge
static __device__ float  d_dinv[N_NODES];
static __device__ float4 d_g   [N_NODES * 4];    // raw h1 (16 floats per node)
static __device__ float4 d_agg [N_NODES * 4];    // raw h2
static __device__ int2   d_edge[E_MAX];          // packed (src, dst)
static __device__ int    d_csr [E_MAX];          // src ids grouped by dst
static __device__ int    d_rs  [N_NODES + 1];    // CSR row starts
static __device__ int    d_cur [N_NODES];        // fill cursors
static __device__ int    d_part[512];            // block sums for scan
static __device__ float  d_p   [N_NODES];
static __device__ float  d_q   [N_NODES];

// ---------------------------------------------------------------- cp.async helpers
__device__ __forceinline__ void cp_async4(unsigned int smem_addr, const void* gptr, int src_bytes) {
    asm volatile("cp.async.ca.shared.global [%0], [%1], 4, %2;"
                 :: "r"(smem_addr), "l"(gptr), "r"(src_bytes));
}
__device__ __forceinline__ void cp_commit() {
    asm volatile("cp.async.commit_group;");
}
template <int N>
__device__ __forceinline__ void cp_wait() {
    asm volatile("cp.async.wait_group %0;" :: "n"(N));
}

// ---------------------------------------------------------------- launch 0: decode + degree count
__global__ void k_conv(const void* __restrict__ ei, int e, int n) {
    __shared__ int s_is64;
    if (threadIdx.x < 32) {
        const int* w = (const int*)ei;
        int x = w[2 * threadIdx.x + 1];
        unsigned any = __ballot_sync(0xffffffffu, x != 0);
        if (threadIdx.x == 0) s_is64 = (any == 0u);
    }
    __syncthreads();
    int i = blockIdx.x * blockDim.x + threadIdx.x;
    if (i >= e) return;
    int s, d;
    if (s_is64) {
        const long long* p = (const long long*)ei;
        s = (int)p[i];
        d = (int)p[e + i];
    } else {
        const int* p = (const int*)ei;
        s = p[i];
        d = p[e + i];
    }
    if ((unsigned)s >= (unsigned)n) s = 0;
    if ((unsigned)d >= (unsigned)n) d = 0;
    d_edge[i] = make_int2(s, d);
    atomicAdd(&d_cnt[d], 1);
}

// ---------------------------------------------------------------- launch 1: 256-chunk sums
__global__ void k_scan1(int n) {
    __shared__ int sh[256];
    int t = threadIdx.x;
    int v = blockIdx.x * 256 + t;
    sh[t] = (v < n) ? d_cnt[v] : 0;
    __syncthreads();
    for (int st = 128; st > 0; st >>= 1) {
        if (t < st) sh[t] += sh[t + st];
        __syncthreads();
    }
    if (t == 0) d_part[blockIdx.x] = sh[0];
}

// ---------------------------------------------------------------- launch 2: row starts + cursors + dinv
__global__ void k_scan3(int n, int nb) {
    __shared__ int sh[256];
    __shared__ int soff;
    int t = threadIdx.x;
    int part = 0;
    for (int i = t; i < blockIdx.x; i += 256) part += d_part[i];
    sh[t] = part;
    __syncthreads();
    for (int st = 128; st > 0; st >>= 1) {
        if (t < st) sh[t] += sh[t + st];
        __syncthreads();
    }
    if (t == 0) soff = sh[0];
    __syncthreads();

    int v = blockIdx.x * 256 + t;
    int c = (v < n) ? d_cnt[v] : 0;
    sh[t] = c;
    __syncthreads();
    for (int off = 1; off < 256; off <<= 1) {
        int xv = (t >= off) ? sh[t - off] : 0;
        __syncthreads();
        sh[t] += xv;
        __syncthreads();
    }
    if (v < n) {
        int excl = soff + sh[t] - c;
        d_rs[v]  = excl;
        d_cur[v] = excl;
        d_dinv[v] = rsqrtf(1.0f + (float)c);   // +1 self loop
        if (v == n - 1) d_rs[n] = excl + c;
    }
}

// ---------------------------------------------------------------- launch 3 (PROFILED): GEMM1, h1 = x @ W1 (raw)
#define GM_THREADS 256
#define GM_ROWS    64
#define GM_TILEK   64
#define GM_NT      8            // 8 * 64 = 512 >= 495
#define GM_XPITCH  68
#define GM_XBUF    (GM_ROWS * GM_XPITCH)   // 4352 floats
#define GM_KPAD    512
#define GM_SMEM_FLOATS (GM_KPAD * FH + 2 * GM_XBUF)   // 67.6KB

__global__ void __launch_bounds__(GM_THREADS, 3) k_gemm1(const float* __restrict__ x,
                                                         const float* __restrict__ W1, int n) {
    extern __shared__ float sm[];
    float* Ws = sm;                         // [512][16] zero-padded
    float* xb[2] = { sm + GM_KPAD * FH, sm + GM_KPAD * FH + GM_XBUF };

    int tid  = threadIdx.x;
    int lane = tid & 31;
    int warp = tid >> 5;
    int row0 = blockIdx.x * GM_ROWS;
    int rloc  = (warp & 1) * 32 + lane;     // 0..63
    int row   = row0 + rloc;
    int quart = warp >> 1;                  // K-quarter 0..3
    bool owner = (quart == 0);

    for (int i = tid; i < GM_KPAD * FH; i += GM_THREADS)
        Ws[i] = (i < F_IN * FH) ? W1[i] : 0.0f;

    int scol = tid & 63;
    int srg  = tid >> 6;

    unsigned int xb_s[2];
    xb_s[0] = (unsigned int)__cvta_generic_to_shared(xb[0]);
    xb_s[1] = (unsigned int)__cvta_generic_to_shared(xb[1]);

    float acc[FH];
#pragma unroll
    for (int j = 0; j < FH; j++) acc[j] = 0.0f;

    {
        int gk = scol;
        bool kok = (gk < F_IN);
#pragma unroll
        for (int p = 0; p < 16; p++) {
            int r  = srg + 4 * p;
            int gr = row0 + r;
            int ok = (gr < n && kok) ? 4 : 0;
            const float* src = x + ((long long)(ok ? gr : 0)) * F_IN + (ok ? gk : 0);
            cp_async4(xb_s[0] + (unsigned int)(r * GM_XPITCH + scol) * 4u, src, ok);
        }
        cp_commit();
    }

#pragma unroll
    for (int t = 0; t < GM_NT; t++) {
        int cur = t & 1;
        if (t + 1 < GM_NT) {
            int gk = (t + 1) * GM_TILEK + scol;
            bool kok = (gk < F_IN);
            int nxt = (t + 1) & 1;
#pragma unroll
            for (int p = 0; p < 16; p++) {
                int r  = srg + 4 * p;
                int gr = row0 + r;
                int ok = (gr < n && kok) ? 4 : 0;
                const float* src = x + ((long long)(ok ? gr : 0)) * F_IN + (ok ? gk : 0);
                cp_async4(xb_s[nxt] + (unsigned int)(r * GM_XPITCH + scol) * 4u, src, ok);
            }
            cp_commit();
            cp_wait<1>();
        } else {
            cp_wait<0>();
        }
        __syncthreads();

        const float4* xr = (const float4*)(xb[cur] + rloc * GM_XPITCH);
        int kq0 = quart * 4;
#pragma unroll
        for (int kq = 0; kq < 4; kq++) {
            float4 xv = xr[kq0 + kq];
            const float4* w4 = (const float4*)(Ws + (t * GM_TILEK + (kq0 + kq) * 4) * FH);
#pragma unroll
            for (int i = 0; i < 4; i++) {
                float xi = (i == 0) ? xv.x : (i == 1) ? xv.y : (i == 2) ? xv.z : xv.w;
                float4 b0 = w4[i * 4 + 0];
                float4 b1 = w4[i * 4 + 1];
                float4 b2 = w4[i * 4 + 2];
                float4 b3 = w4[i * 4 + 3];
                acc[0]  = fmaf(xi, b0.x, acc[0]);
                acc[1]  = fmaf(xi, b0.y, acc[1]);
                acc[2]  = fmaf(xi, b0.z, acc[2]);
                acc[3]  = fmaf(xi, b0.w, acc[3]);
                acc[4]  = fmaf(xi, b1.x, acc[4]);
                acc[5]  = fmaf(xi, b1.y, acc[5]);
                acc[6]  = fmaf(xi, b1.z, acc[6]);
                acc[7]  = fmaf(xi, b1.w, acc[7]);
                acc[8]  = fmaf(xi, b2.x, acc[8]);
                acc[9]  = fmaf(xi, b2.y, acc[9]);
                acc[10] = fmaf(xi, b2.z, acc[10]);
                acc[11] = fmaf(xi, b2.w, acc[11]);
                acc[12] = fmaf(xi, b3.x, acc[12]);
                acc[13] = fmaf(xi, b3.y, acc[13]);
                acc[14] = fmaf(xi, b3.z, acc[14]);
                acc[15] = fmaf(xi, b3.w, acc[15]);
            }
        }
        __syncthreads();
    }

    float* red = xb[0];
    if (!owner) {
        float4* r4 = (float4*)(red + ((quart - 1) * GM_ROWS + rloc) * 16);
#pragma unroll
        for (int qd = 0; qd < 4; qd++)
            r4[qd] = make_float4(acc[4 * qd], acc[4 * qd + 1], acc[4 * qd + 2], acc[4 * qd + 3]);
    }
    __syncthreads();
    if (owner && row < n) {
#pragma unroll
        for (int q = 1; q < 4; q++) {
            const float* rr = red + ((q - 1) * GM_ROWS + rloc) * 16;
#pragma unroll
            for (int j = 0; j < FH; j++) acc[j] += rr[j];
        }
        float4* gp = &d_g[row * 4];
#pragma unroll
        for (int qd = 0; qd < 4; qd++)
            gp[qd] = make_float4(acc[4 * qd], acc[4 * qd + 1],
                                 acc[4 * qd + 2], acc[4 * qd + 3]);
    }
}

// ---------------------------------------------------------------- launch 4: CSR fill
__global__ void k_fill(int e) {
    int i = blockIdx.x * blockDim.x + threadIdx.x;
    if (i >= e) return;
    int2 ed = d_edge[i];
    int pos = atomicAdd(&d_cur[ed.y], 1);
    d_csr[pos] = ed.x;
}

// ---------------------------------------------------------------- launch 5: gather1 + layer1 finalize + layer2 GEMM
// warp per node: agg = h1[v]*dinv[v] + sum_e h1[src]*dinv[src];
// z = relu(dinv[v]*agg + b1); h2 = z @ W2 (warp-cooperative); store raw h2.
__global__ void __launch_bounds__(256) k_gather_mid(const float* __restrict__ W2,
                                                    const float* __restrict__ b1, int n) {
    int lane = threadIdx.x & 31;
    int fl   = lane & 15;

    float w2col[FH];
#pragma unroll
    for (int k = 0; k < FH; k++) w2col[k] = __ldg(W2 + k * FH + fl);
    float b1j = __ldg(b1 + fl);

    int wid = (blockIdx.x * blockDim.x + threadIdx.x) >> 5;
    if (wid >= n) return;
    int v    = wid;
    int base = d_rs[v];
    int dend = d_rs[v + 1];
    int grp  = lane >> 4;
    const float* gf = (const float*)d_g;

    float acc = 0.0f;
    int j = base + grp;
    for (; j + 6 < dend; j += 8) {
        int s0 = d_csr[j];
        int s1 = d_csr[j + 2];
        int s2 = d_csr[j + 4];
        int s3 = d_csr[j + 6];
        float w0 = d_dinv[s0], w1 = d_dinv[s1], w2 = d_dinv[s2], w3 = d_dinv[s3];
        acc = fmaf(gf[s0 * 16 + fl], w0, acc);
        acc = fmaf(gf[s1 * 16 + fl], w1, acc);
        acc = fmaf(gf[s2 * 16 + fl], w2, acc);
        acc = fmaf(gf[s3 * 16 + fl], w3, acc);
    }
    for (; j < dend; j += 2) {
        int s0 = d_csr[j];
        acc = fmaf(gf[s0 * 16 + fl], d_dinv[s0], acc);
    }
    acc += __shfl_down_sync(0xffffffffu, acc, 16);

    float di = d_dinv[v];
    acc = fmaf(gf[v * 16 + fl], di, acc);          // SELF-LOOP term (the R13 bug)
    float z = fmaxf(fmaf(di, acc, b1j), 0.0f);     // valid in lanes 0-15

    float h2 = 0.0f;
#pragma unroll
    for (int k = 0; k < FH; k++) {
        float zk = __shfl_sync(0xffffffffu, z, k);
        h2 = fmaf(zk, w2col[k], h2);
    }
    if (lane < 16) {
        float* af = (float*)d_agg;
        af[v * 16 + fl] = h2;
    }
}

// ---------------------------------------------------------------- launch 6: gather2 + layer2 finalize + separable FC
__global__ void __launch_bounds__(256) k_gather_fin(const float* __restrict__ b2,
                                                    const float* __restrict__ Wfc, int n) {
    int lane = threadIdx.x & 31;
    int fl   = lane & 15;

    float wfp = __ldg(Wfc + fl);
    float wfq = __ldg(Wfc + FH + fl);
    float b2j = __ldg(b2 + fl);

    int wid = (blockIdx.x * blockDim.x + threadIdx.x) >> 5;
    if (wid >= n) return;
    int v    = wid;
    int base = d_rs[v];
    int dend = d_rs[v + 1];
    int grp  = lane >> 4;
    const float* gf = (const float*)d_agg;

    float acc = 0.0f;
    int j = base + grp;
    for (; j + 6 < dend; j += 8) {
        int s0 = d_csr[j];
        int s1 = d_csr[j + 2];
        int s2 = d_csr[j + 4];
        int s3 = d_csr[j + 6];
        float w0 = d_dinv[s0], w1 = d_dinv[s1], w2 = d_dinv[s2], w3 = d_dinv[s3];
        acc = fmaf(gf[s0 * 16 + fl], w0, acc);
        acc = fmaf(gf[s1 * 16 + fl], w1, acc);
        acc = fmaf(gf[s2 * 16 + fl], w2, acc);
        acc = fmaf(gf[s3 * 16 + fl], w3, acc);
    }
    for (; j < dend; j += 2) {
        int s0 = d_csr[j];
        acc = fmaf(gf[s0 * 16 + fl], d_dinv[s0], acc);
    }
    acc += __shfl_down_sync(0xffffffffu, acc, 16);

    float di = d_dinv[v];
    acc = fmaf(gf[v * 16 + fl], di, acc);          // SELF-LOOP term (the R13 bug)
    float z2 = fmaxf(fmaf(di, acc, b2j), 0.0f);    // lanes 0-15

    float tp = z2 * wfp;
    float tq = z2 * wfq;
#pragma unroll
    for (int off = 8; off > 0; off >>= 1) {
        tp += __shfl_down_sync(0xffffffffu, tp, off);
        tq += __shfl_down_sync(0xffffffffu, tq, off);
    }
    if (lane == 0) {
        d_p[v] = tp;
        d_q[v] = tq;
    }
}

// ---------------------------------------------------------------- launch 7: out[e] = p[src] + q[dst] + bfc; re-zero d_cnt
__global__ void k_edge(const float* __restrict__ bfc, float* __restrict__ out, int e) {
    int i = blockIdx.x * blockDim.x + threadIdx.x;
    if (i < N_NODES) d_cnt[i] = 0;              // leave state clean for next replay
    if (i >= e) return;
    float b = __ldg(bfc);
    int2 ed = d_edge[i];
    out[i] = d_p[ed.x] + d_q[ed.y] + b;
}

// ----------------------------------------------------------------
extern "C" void kernel_launch(void* const* d_in, const int* in_sizes, int n_in,
                              void* d_out, int out_size) {
    const float* x    = (const float*)d_in[0];
    const void*  ei   = d_in[1];
    const float* W1   = (const float*)d_in[2];
    const float* b1   = (const float*)d_in[3];
    const float* W2   = (const float*)d_in[4];
    const float* b2   = (const float*)d_in[5];
    const float* Wfc  = (const float*)d_in[6];
    const float* bfc  = (const float*)d_in[7];
    float*       out  = (float*)d_out;

    int n = in_sizes[0] / F_IN;      // 100000
    int e = in_sizes[1] / 2;         // 3200000

    static const int smem_bytes = GM_SMEM_FLOATS * (int)sizeof(float);
    cudaFuncSetAttribute(k_gemm1, cudaFuncAttributeMaxDynamicSharedMemorySize, smem_bytes);

    int nb_n  = (n + 255) / 256;                 // 391
    int nb_e  = (e + 255) / 256;
    int nb_gm = (n + GM_ROWS - 1) / GM_ROWS;     // 1563
    int nb_gw = (n * 32 + 255) / 256;            // warp per node

    k_conv <<<nb_e, 256>>>(ei, e, n);                        // 0
    k_scan1<<<nb_n, 256>>>(n);                               // 1
    k_scan3<<<nb_n, 256>>>(n, nb_n);                         // 2
    k_gemm1<<<nb_gm, GM_THREADS, smem_bytes>>>(x, W1, n);    // 3  <- profiled slot
    k_fill <<<nb_e, 256>>>(e);                               // 4
    k_gather_mid<<<nb_gw, 256>>>(W2, b1, n);                 // 5
    k_gather_fin<<<nb_gw, 256>>>(b2, Wfc, n);                // 6
    k_edge <<<nb_e, 256>>>(bfc, out, e);                     // 7
}

// round 17
// speedup vs baseline: 1.0785x; 1.0785x over previous
#include <cuda_runtime.h>
#include <cstdint>

#define N_NODES 100000
#define E_MAX   3200000
#define F_IN    495
#define FH      16

// ---- scratch (no device allocations allowed) ----
static __device__ int    d_cnt [N_NODES];        // zero at load; re-zeroed by k_edge each call
static __device__ float  d_dinv[N_NODES];
static __device__ float4 d_g   [N_NODES * 4];    // raw h1 / raw h2
static __device__ float4 d_agg [N_NODES * 4];    // aggregated
static __device__ int2   d_edge[E_MAX];          // packed (src, dst)
static __device__ int    d_csr [E_MAX];          // src ids grouped by dst
static __device__ int    d_rs  [N_NODES + 1];    // CSR row starts
static __device__ int    d_cur [N_NODES];        // fill cursors
static __device__ int    d_part[512];            // block sums for scan
static __device__ float  d_p   [N_NODES];
static __device__ float  d_q   [N_NODES];

// ---------------------------------------------------------------- cp.async helpers
__device__ __forceinline__ void cp_async4(unsigned int smem_addr, const void* gptr, int src_bytes) {
    asm volatile("cp.async.ca.shared.global [%0], [%1], 4, %2;"
                 :: "r"(smem_addr), "l"(gptr), "r"(src_bytes));
}
__device__ __forceinline__ void cp_commit() {
    asm volatile("cp.async.commit_group;");
}
template <int N>
__device__ __forceinline__ void cp_wait() {
    asm volatile("cp.async.wait_group %0;" :: "n"(N));
}

// ---------------------------------------------------------------- launch 0: decode + degree count
__global__ void k_conv(const void* __restrict__ ei, int e, int n) {
    __shared__ int s_is64;
    if (threadIdx.x < 32) {
        const int* w = (const int*)ei;
        int x = w[2 * threadIdx.x + 1];
        unsigned any = __ballot_sync(0xffffffffu, x != 0);
        if (threadIdx.x == 0) s_is64 = (any == 0u);
    }
    __syncthreads();
    int i = blockIdx.x * blockDim.x + threadIdx.x;
    if (i >= e) return;
    int s, d;
    if (s_is64) {
        const long long* p = (const long long*)ei;
        s = (int)p[i];
        d = (int)p[e + i];
    } else {
        const int* p = (const int*)ei;
        s = p[i];
        d = p[e + i];
    }
    if ((unsigned)s >= (unsigned)n) s = 0;
    if ((unsigned)d >= (unsigned)n) d = 0;
    d_edge[i] = make_int2(s, d);
    atomicAdd(&d_cnt[d], 1);
}

// ---------------------------------------------------------------- launch 1: 256-chunk sums
__global__ void k_scan1(int n) {
    __shared__ int sh[256];
    int t = threadIdx.x;
    int v = blockIdx.x * 256 + t;
    sh[t] = (v < n) ? d_cnt[v] : 0;
    __syncthreads();
    for (int st = 128; st > 0; st >>= 1) {
        if (t < st) sh[t] += sh[t + st];
        __syncthreads();
    }
    if (t == 0) d_part[blockIdx.x] = sh[0];
}

// ---------------------------------------------------------------- launch 2: row starts + cursors + dinv
__global__ void k_scan3(int n, int nb) {
    __shared__ int sh[256];
    __shared__ int soff;
    int t = threadIdx.x;
    int part = 0;
    for (int i = t; i < blockIdx.x; i += 256) part += d_part[i];
    sh[t] = part;
    __syncthreads();
    for (int st = 128; st > 0; st >>= 1) {
        if (t < st) sh[t] += sh[t + st];
        __syncthreads();
    }
    if (t == 0) soff = sh[0];
    __syncthreads();

    int v = blockIdx.x * 256 + t;
    int c = (v < n) ? d_cnt[v] : 0;
    sh[t] = c;
    __syncthreads();
    for (int off = 1; off < 256; off <<= 1) {
        int xv = (t >= off) ? sh[t - off] : 0;
        __syncthreads();
        sh[t] += xv;
        __syncthreads();
    }
    if (v < n) {
        int excl = soff + sh[t] - c;
        d_rs[v]  = excl;
        d_cur[v] = excl;
        d_dinv[v] = rsqrtf(1.0f + (float)c);   // +1 self loop
        if (v == n - 1) d_rs[n] = excl + c;
    }
}

// ---------------------------------------------------------------- launch 3 (PROFILED): GEMM1, h1 = x @ W1 (raw)
// R12 config (measured 109us): GM_ROWS=64, TILEK=64, 4-way K-split, 3 blocks/SM.
#define GM_THREADS 256
#define GM_ROWS    64
#define GM_TILEK   64
#define GM_NT      8            // 8 * 64 = 512 >= 495
#define GM_XPITCH  68
#define GM_XBUF    (GM_ROWS * GM_XPITCH)   // 4352 floats
#define GM_KPAD    512
#define GM_SMEM_FLOATS (GM_KPAD * FH + 2 * GM_XBUF)   // 67.6KB

__global__ void __launch_bounds__(GM_THREADS, 3) k_gemm1(const float* __restrict__ x,
                                                         const float* __restrict__ W1, int n) {
    extern __shared__ float sm[];
    float* Ws = sm;                         // [512][16] zero-padded
    float* xb[2] = { sm + GM_KPAD * FH, sm + GM_KPAD * FH + GM_XBUF };

    int tid  = threadIdx.x;
    int lane = tid & 31;
    int warp = tid >> 5;
    int row0 = blockIdx.x * GM_ROWS;
    int rloc  = (warp & 1) * 32 + lane;     // 0..63
    int row   = row0 + rloc;
    int quart = warp >> 1;                  // K-quarter 0..3
    bool owner = (quart == 0);

    for (int i = tid; i < GM_KPAD * FH; i += GM_THREADS)
        Ws[i] = (i < F_IN * FH) ? W1[i] : 0.0f;

    int scol = tid & 63;
    int srg  = tid >> 6;

    unsigned int xb_s[2];
    xb_s[0] = (unsigned int)__cvta_generic_to_shared(xb[0]);
    xb_s[1] = (unsigned int)__cvta_generic_to_shared(xb[1]);

    float acc[FH];
#pragma unroll
    for (int j = 0; j < FH; j++) acc[j] = 0.0f;

    {
        int gk = scol;
        bool kok = (gk < F_IN);
#pragma unroll
        for (int p = 0; p < 16; p++) {
            int r  = srg + 4 * p;
            int gr = row0 + r;
            int ok = (gr < n && kok) ? 4 : 0;
            const float* src = x + ((long long)(ok ? gr : 0)) * F_IN + (ok ? gk : 0);
            cp_async4(xb_s[0] + (unsigned int)(r * GM_XPITCH + scol) * 4u, src, ok);
        }
        cp_commit();
    }

#pragma unroll
    for (int t = 0; t < GM_NT; t++) {
        int cur = t & 1;
        if (t + 1 < GM_NT) {
            int gk = (t + 1) * GM_TILEK + scol;
            bool kok = (gk < F_IN);
            int nxt = (t + 1) & 1;
#pragma unroll
            for (int p = 0; p < 16; p++) {
                int r  = srg + 4 * p;
                int gr = row0 + r;
                int ok = (gr < n && kok) ? 4 : 0;
                const float* src = x + ((long long)(ok ? gr : 0)) * F_IN + (ok ? gk : 0);
                cp_async4(xb_s[nxt] + (unsigned int)(r * GM_XPITCH + scol) * 4u, src, ok);
            }
            cp_commit();
            cp_wait<1>();
        } else {
            cp_wait<0>();
        }
        __syncthreads();

        const float4* xr = (const float4*)(xb[cur] + rloc * GM_XPITCH);
        int kq0 = quart * 4;
#pragma unroll
        for (int kq = 0; kq < 4; kq++) {
            float4 xv = xr[kq0 + kq];
            const float4* w4 = (const float4*)(Ws + (t * GM_TILEK + (kq0 + kq) * 4) * FH);
#pragma unroll
            for (int i = 0; i < 4; i++) {
                float xi = (i == 0) ? xv.x : (i == 1) ? xv.y : (i == 2) ? xv.z : xv.w;
                float4 b0 = w4[i * 4 + 0];
                float4 b1 = w4[i * 4 + 1];
                float4 b2 = w4[i * 4 + 2];
                float4 b3 = w4[i * 4 + 3];
                acc[0]  = fmaf(xi, b0.x, acc[0]);
                acc[1]  = fmaf(xi, b0.y, acc[1]);
                acc[2]  = fmaf(xi, b0.z, acc[2]);
                acc[3]  = fmaf(xi, b0.w, acc[3]);
                acc[4]  = fmaf(xi, b1.x, acc[4]);
                acc[5]  = fmaf(xi, b1.y, acc[5]);
                acc[6]  = fmaf(xi, b1.z, acc[6]);
                acc[7]  = fmaf(xi, b1.w, acc[7]);
                acc[8]  = fmaf(xi, b2.x, acc[8]);
                acc[9]  = fmaf(xi, b2.y, acc[9]);
                acc[10] = fmaf(xi, b2.z, acc[10]);
                acc[11] = fmaf(xi, b2.w, acc[11]);
                acc[12] = fmaf(xi, b3.x, acc[12]);
                acc[13] = fmaf(xi, b3.y, acc[13]);
                acc[14] = fmaf(xi, b3.z, acc[14]);
                acc[15] = fmaf(xi, b3.w, acc[15]);
            }
        }
        __syncthreads();
    }

    float* red = xb[0];
    if (!owner) {
        float4* r4 = (float4*)(red + ((quart - 1) * GM_ROWS + rloc) * 16);
#pragma unroll
        for (int qd = 0; qd < 4; qd++)
            r4[qd] = make_float4(acc[4 * qd], acc[4 * qd + 1], acc[4 * qd + 2], acc[4 * qd + 3]);
    }
    __syncthreads();
    if (owner && row < n) {
#pragma unroll
        for (int q = 1; q < 4; q++) {
            const float* rr = red + ((q - 1) * GM_ROWS + rloc) * 16;
#pragma unroll
            for (int j = 0; j < FH; j++) acc[j] += rr[j];
        }
        float4* gp = &d_g[row * 4];
#pragma unroll
        for (int qd = 0; qd < 4; qd++)
            gp[qd] = make_float4(acc[4 * qd], acc[4 * qd + 1],
                                 acc[4 * qd + 2], acc[4 * qd + 3]);
    }
}

// ---------------------------------------------------------------- launch 4: CSR fill
__global__ void k_fill(int e) {
    int i = blockIdx.x * blockDim.x + threadIdx.x;
    if (i >= e) return;
    int2 ed = d_edge[i];
    int pos = atomicAdd(&d_cur[ed.y], 1);
    d_csr[pos] = ed.x;
}

// ---------------------------------------------------------------- gather: agg[v] = g[v]*dinv[v] + sum_e g[src]*dinv[src]
// NO pointer args — references device globals directly (host can't take &__device__).
__global__ void __launch_bounds__(256) k_gather(int n) {
    int wid  = (blockIdx.x * blockDim.x + threadIdx.x) >> 5;
    int lane = threadIdx.x & 31;
    if (wid >= n) return;
    int v    = wid;
    int base = d_rs[v];
    int dend = d_rs[v + 1];
    int grp  = lane >> 4;
    int fl   = lane & 15;
    const float* gf = (const float*)d_g;

    float acc = 0.0f;
    int j = base + grp;
    for (; j + 6 < dend; j += 8) {
        int s0 = d_csr[j];
        int s1 = d_csr[j + 2];
        int s2 = d_csr[j + 4];
        int s3 = d_csr[j + 6];
        float w0 = d_dinv[s0], w1 = d_dinv[s1], w2 = d_dinv[s2], w3 = d_dinv[s3];
        acc = fmaf(gf[s0 * 16 + fl], w0, acc);
        acc = fmaf(gf[s1 * 16 + fl], w1, acc);
        acc = fmaf(gf[s2 * 16 + fl], w2, acc);
        acc = fmaf(gf[s3 * 16 + fl], w3, acc);
    }
    for (; j < dend; j += 2) {
        int s0 = d_csr[j];
        acc = fmaf(gf[s0 * 16 + fl], d_dinv[s0], acc);
    }
    acc += __shfl_down_sync(0xffffffffu, acc, 16);
    if (lane < 16) {
        float* af = (float*)d_agg;
        af[v * 16 + fl] = fmaf(gf[v * 16 + fl], d_dinv[v], acc);
    }
}

// ---------------------------------------------------------------- layer1 finalize + layer2 GEMM -> d_g (raw h2)
__global__ void __launch_bounds__(256) k_mid(const float* __restrict__ W2,
                                             const float* __restrict__ b1, int n) {
    __shared__ float w2s[FH * FH];
    __shared__ float b1s[FH];
    int tid = threadIdx.x;
    if (tid < FH * FH) w2s[tid] = W2[tid];
    if (tid < FH) b1s[tid] = b1[tid];
    __syncthreads();

    int v = blockIdx.x * blockDim.x + tid;
    if (v >= n) return;
    float di = d_dinv[v];
    const float4* ap = &d_agg[v * 4];
    float z[FH];
#pragma unroll
    for (int qd = 0; qd < 4; qd++) {
        float4 a = ap[qd];
        z[4 * qd + 0] = fmaxf(fmaf(di, a.x, b1s[4 * qd + 0]), 0.0f);
        z[4 * qd + 1] = fmaxf(fmaf(di, a.y, b1s[4 * qd + 1]), 0.0f);
        z[4 * qd + 2] = fmaxf(fmaf(di, a.z, b1s[4 * qd + 2]), 0.0f);
        z[4 * qd + 3] = fmaxf(fmaf(di, a.w, b1s[4 * qd + 3]), 0.0f);
    }
    float h[FH];
#pragma unroll
    for (int j = 0; j < FH; j++) h[j] = 0.0f;
#pragma unroll
    for (int k = 0; k < FH; k++) {
        float zk = z[k];
#pragma unroll
        for (int j = 0; j < FH; j++) h[j] = fmaf(zk, w2s[k * FH + j], h[j]);
    }
    float4* gp = &d_g[v * 4];
#pragma unroll
    for (int qd = 0; qd < 4; qd++)
        gp[qd] = make_float4(h[4 * qd], h[4 * qd + 1], h[4 * qd + 2], h[4 * qd + 3]);
}

// ---------------------------------------------------------------- layer2 finalize + separable FC
__global__ void __launch_bounds__(256) k_fin2(const float* __restrict__ b2,
                                              const float* __restrict__ Wfc, int n) {
    __shared__ float wfs[2 * FH];
    __shared__ float b2s[FH];
    int tid = threadIdx.x;
    if (tid < 2 * FH) wfs[tid] = Wfc[tid];
    if (tid < FH) b2s[tid] = b2[tid];
    __syncthreads();

    int v = blockIdx.x * blockDim.x + tid;
    if (v >= n) return;
    float di = d_dinv[v];
    const float4* ap = &d_agg[v * 4];
    float p = 0.0f, q = 0.0f;
#pragma unroll
    for (int qd = 0; qd < 4; qd++) {
        float4 a = ap[qd];
        float zz[4];
        zz[0] = fmaxf(fmaf(di, a.x, b2s[4 * qd + 0]), 0.0f);
        zz[1] = fmaxf(fmaf(di, a.y, b2s[4 * qd + 1]), 0.0f);
        zz[2] = fmaxf(fmaf(di, a.z, b2s[4 * qd + 2]), 0.0f);
        zz[3] = fmaxf(fmaf(di, a.w, b2s[4 * qd + 3]), 0.0f);
#pragma unroll
        for (int u = 0; u < 4; u++) {
            p = fmaf(zz[u], wfs[4 * qd + u], p);
            q = fmaf(zz[u], wfs[FH + 4 * qd + u], q);
        }
    }
    d_p[v] = p;
    d_q[v] = q;
}

// ---------------------------------------------------------------- out[e] = p[src] + q[dst] + bfc; re-zero d_cnt
__global__ void k_edge(const float* __restrict__ bfc, float* __restrict__ out, int e) {
    int i = blockIdx.x * blockDim.x + threadIdx.x;
    if (i < N_NODES) d_cnt[i] = 0;
    if (i >= e) return;
    float b = __ldg(bfc);
    int2 ed = d_edge[i];
    out[i] = d_p[ed.x] + d_q[ed.y] + b;
}

// ----------------------------------------------------------------
extern "C" void kernel_launch(void* const* d_in, const int* in_sizes, int n_in,
                              void* d_out, int out_size) {
    const float* x    = (const float*)d_in[0];
    const void*  ei   = d_in[1];
    const float* W1   = (const float*)d_in[2];
    const float* b1   = (const float*)d_in[3];
    const float* W2   = (const float*)d_in[4];
    const float* b2   = (const float*)d_in[5];
    const float* Wfc  = (const float*)d_in[6];
    const float* bfc  = (const float*)d_in[7];
    float*       out  = (float*)d_out;

    int n = in_sizes[0] / F_IN;      // 100000
    int e = in_sizes[1] / 2;         // 3200000

    static const int smem_bytes = GM_SMEM_FLOATS * (int)sizeof(float);
    cudaFuncSetAttribute(k_gemm1, cudaFuncAttributeMaxDynamicSharedMemorySize, smem_bytes);

    int nb_n  = (n + 255) / 256;                 // 391
    int nb_e  = (e + 255) / 256;
    int nb_gm = (n + GM_ROWS - 1) / GM_ROWS;     // 1563
    int nb_gw = (n * 32 + 255) / 256;            // warp per node

    k_conv <<<nb_e, 256>>>(ei, e, n);                        // 0
    k_scan1<<<nb_n, 256>>>(n);                               // 1
    k_scan3<<<nb_n, 256>>>(n, nb_n);                         // 2
    k_gemm1<<<nb_gm, GM_THREADS, smem_bytes>>>(x, W1, n);    // 3  <- profiled slot
    k_fill <<<nb_e, 256>>>(e);                               // 4
    k_gather<<<nb_gw, 256>>>(n);                             // 5
    k_mid  <<<nb_n, 256>>>(W2, b1, n);                       // 6
    k_gather<<<nb_gw, 256>>>(n);                             // 7
    k_fin2 <<<nb_n, 256>>>(b2, Wfc, n);                      // 8
    k_edge <<<nb_e, 256>>>(bfc, out, e);                     // 9
}